// round 13
// baseline (speedup 1.0000x reference)
#include <cuda_runtime.h>

#define BB 4
#define NN 4096
#define HH 16
#define DD 64
#define HD (HH*DD)          // 1024
#define BH (BB*HH)          // 64
#define CH 16
#define CHTOK (NN/CH)       // 256
#define EPSZ 1e-6f
#define NTILE (BB*NN/64)    // 256 token tiles

#define KVSTR 72            // ==8 mod 32: conflict-free frags
#define QSTR  68            // ==4 mod 32
#define CSTR  72

#define KV_TILE_F (32*KVSTR)                        // floats per stage per tensor
#define KV_SMEM ((6*KV_TILE_F + 16*64) * (int)sizeof(float))   // 59,392 B

__device__ float g_KVpart[CH*BH*DD*DD];   // 16 MB
__device__ float g_KSpart[CH*BH*DD];
__device__ float g_C[BH*DD*DD];           // tf32-rna-pre-rounded
__device__ float g_Ksum[BH*DD];
__device__ int   g_cnt[BH];               // zero-init; self-resetting per launch

__device__ __forceinline__ float phi(float x) { return x > 0.0f ? x + 1.0f : __expf(x); }

__device__ __forceinline__ float tf32r(float x) {
    unsigned u;
    asm("cvt.rna.tf32.f32 %0, %1;" : "=r"(u) : "f"(x));
    return __uint_as_float(u);
}
__device__ __forceinline__ float4 phi4(float4 v) {
    float4 r; r.x = phi(v.x); r.y = phi(v.y); r.z = phi(v.z); r.w = phi(v.w);
    return r;
}
__device__ __forceinline__ float4 r4(float4 v) {
    float4 r; r.x = tf32r(v.x); r.y = tf32r(v.y); r.z = tf32r(v.z); r.w = tf32r(v.w);
    return r;
}

__device__ __forceinline__ void mma_tf32(float c[4],
    unsigned a0, unsigned a1, unsigned a2, unsigned a3,
    unsigned b0, unsigned b1)
{
    asm volatile(
        "mma.sync.aligned.m16n8k8.row.col.f32.tf32.tf32.f32 "
        "{%0,%1,%2,%3},{%4,%5,%6,%7},{%8,%9},{%0,%1,%2,%3};"
        : "+f"(c[0]), "+f"(c[1]), "+f"(c[2]), "+f"(c[3])
        : "r"(a0), "r"(a1), "r"(a2), "r"(a3), "r"(b0), "r"(b1));
}
__device__ __forceinline__ unsigned fb(float x) { return __float_as_uint(x); }

__device__ __forceinline__ void cpa16(void* smem, const void* g) {
    unsigned s = (unsigned)__cvta_generic_to_shared(smem);
    asm volatile("cp.async.ca.shared.global [%0], [%1], 16;" :: "r"(s), "l"(g));
}
#define CP_COMMIT() asm volatile("cp.async.commit_group;")
#define CP_WAIT(n)  asm volatile("cp.async.wait_group %0;" :: "n"(n))
#define BAR_GRP(id) asm volatile("bar.sync %0, 128;" :: "r"(id) : "memory")

// ---------------------------------------------------------------------------
// Phase 1 + fold: partial KV[d][m] = sum_t phi(K[t][d]) * V[t][m], tf32 MMA.
// 3-stage cp.async ring, ONE barrier per tile (the post-RMW barrier also
// certifies all warps finished the previous MMA, making stage (tile-1)%3
// safe to refill). Last block per bh reduces all chunk partials and runs
// the W-fold inline (atomic counter, release/acquire fences, self-reset).
// 1024 blocks x 256 threads, 59KB dynamic smem.
// ---------------------------------------------------------------------------
__global__ __launch_bounds__(256, 3) void kv_partial_kernel(
    const float* __restrict__ key, const float* __restrict__ value,
    const float* __restrict__ W_out)
{
    extern __shared__ float sm[];
    float* KsB   = sm;                     // 3 stages x 32 x KVSTR
    float* VsB   = sm + 3 * KV_TILE_F;
    float* kpart = sm + 6 * KV_TILE_F;     // 16 x 64
    __shared__ int slast;

    const int bx  = blockIdx.x;
    const int c   = bx % CH;
    const int bh  = bx / CH;
    const int b   = bh / HH;
    const int h   = bh % HH;
    const int tid = threadIdx.x;
    const int lane = tid & 31, warp = tid >> 5;
    const int dRow = (warp & 3) * 16;
    const int mCol = (warp >> 2) * 32;
    const int ar = lane >> 2;
    const int ac = lane & 3;

    const int t0i = tid >> 4;        // 0..15
    const int t1i = t0i + 16;
    const int d4  = (tid & 15) * 4;

    const int n0 = c * CHTOK;
    const size_t gbase = (size_t)(b * NN + n0) * HD + h * DD + d4;
    const float* kp0 = key   + gbase + (size_t)t0i * HD;
    const float* kp1 = key   + gbase + (size_t)t1i * HD;
    const float* vp0 = value + gbase + (size_t)t0i * HD;
    const float* vp1 = value + gbase + (size_t)t1i * HD;

    float acc[4][4];
#pragma unroll
    for (int nt = 0; nt < 4; nt++)
#pragma unroll
        for (int j = 0; j < 4; j++) acc[nt][j] = 0.0f;

    float4 ks4 = make_float4(0.f, 0.f, 0.f, 0.f);

    // prologue: tiles 0,1 into stages 0,1 (separate commit groups)
#pragma unroll
    for (int s = 0; s < 2; s++) {
        const size_t off = (size_t)s * 32 * HD;
        cpa16(KsB + s * KV_TILE_F + t0i * KVSTR + d4, kp0 + off);
        cpa16(KsB + s * KV_TILE_F + t1i * KVSTR + d4, kp1 + off);
        cpa16(VsB + s * KV_TILE_F + t0i * KVSTR + d4, vp0 + off);
        cpa16(VsB + s * KV_TILE_F + t1i * KVSTR + d4, vp1 + off);
        CP_COMMIT();
    }

    const int NT = CHTOK / 32;       // 8
    int cur = 0;
    for (int tile = 0; tile < NT; tile++) {
        if (tile + 1 < NT) { CP_WAIT(1); } else { CP_WAIT(0); }

        float* Kc = KsB + cur * KV_TILE_F;
        float* Vc = VsB + cur * KV_TILE_F;

        // RMW convert own chunks; accumulate Ksum from registers
        {
            const float4 p0 = phi4(*(const float4*)(Kc + t0i * KVSTR + d4));
            const float4 p1 = phi4(*(const float4*)(Kc + t1i * KVSTR + d4));
            *(float4*)(Kc + t0i * KVSTR + d4) = r4(p0);
            *(float4*)(Kc + t1i * KVSTR + d4) = r4(p1);
            ks4.x += p0.x + p1.x; ks4.y += p0.y + p1.y;
            ks4.z += p0.z + p1.z; ks4.w += p0.w + p1.w;
            *(float4*)(Vc + t0i * KVSTR + d4) = r4(*(const float4*)(Vc + t0i * KVSTR + d4));
            *(float4*)(Vc + t1i * KVSTR + d4) = r4(*(const float4*)(Vc + t1i * KVSTR + d4));
        }
        __syncthreads();   // all warps: RMW(cur) done AND MMA(tile-1) done

        // refill stage (tile+2)%3 == (tile-1)%3 (its MMA is certified done)
        if (tile + 2 < NT) {
            int nst = cur + 2; if (nst >= 3) nst -= 3;
            const size_t off = (size_t)(tile + 2) * 32 * HD;
            cpa16(KsB + nst * KV_TILE_F + t0i * KVSTR + d4, kp0 + off);
            cpa16(KsB + nst * KV_TILE_F + t1i * KVSTR + d4, kp1 + off);
            cpa16(VsB + nst * KV_TILE_F + t0i * KVSTR + d4, vp0 + off);
            cpa16(VsB + nst * KV_TILE_F + t1i * KVSTR + d4, vp1 + off);
            CP_COMMIT();
        }

#pragma unroll
        for (int kk = 0; kk < 4; kk++) {
            const int k0 = kk * 8;
            const unsigned a0 = fb(Kc[(k0 + ac    ) * KVSTR + dRow + ar    ]);
            const unsigned a1 = fb(Kc[(k0 + ac    ) * KVSTR + dRow + ar + 8]);
            const unsigned a2 = fb(Kc[(k0 + ac + 4) * KVSTR + dRow + ar    ]);
            const unsigned a3 = fb(Kc[(k0 + ac + 4) * KVSTR + dRow + ar + 8]);
#pragma unroll
            for (int nt = 0; nt < 4; nt++) {
                const int nc = mCol + nt * 8 + ar;
                const unsigned b0 = fb(Vc[(k0 + ac    ) * KVSTR + nc]);
                const unsigned b1 = fb(Vc[(k0 + ac + 4) * KVSTR + nc]);
                mma_tf32(acc[nt], a0, a1, a2, a3, b0, b1);
            }
        }
        cur = (cur == 2) ? 0 : cur + 1;
    }
    __syncthreads();

    // Ksum partial reduce (each thread owns unique (t0i, d4) slot)
    *(float4*)(kpart + t0i * 64 + d4) = ks4;
    __syncthreads();
    if (tid < 64) {
        float s = 0.0f;
#pragma unroll
        for (int r = 0; r < 16; r++) s += kpart[r * 64 + tid];
        g_KSpart[(c * BH + bh) * DD + tid] = s;
    }

    float* outp = g_KVpart + (size_t)(c * BH + bh) * DD * DD;
#pragma unroll
    for (int nt = 0; nt < 4; nt++) {
        const int col = mCol + nt * 8 + 2 * ac;
        const int r0  = dRow + ar;
        *(float2*)(outp + r0 * DD + col)       = make_float2(acc[nt][0], acc[nt][1]);
        *(float2*)(outp + (r0 + 8) * DD + col) = make_float2(acc[nt][2], acc[nt][3]);
    }

    // -------- last-block-per-bh inline fold --------
    __threadfence();                 // release: partials visible device-wide
    __syncthreads();                 // all threads' writes+fences done
    if (tid == 0)
        slast = (atomicAdd(&g_cnt[bh], 1) == CH - 1) ? 1 : 0;
    __syncthreads();
    if (!slast) return;
    __threadfence();                 // acquire side

    // reuse smem: KVs [64][68] at sm, Ws [64][68] at sm + 4352
    float* KVs = sm;
    float* Ws  = sm + 64 * 68;

#pragma unroll
    for (int i = 0; i < 4; i++) {
        const int lin = (tid + i * 256) * 4;
        float4 s = make_float4(0.f, 0.f, 0.f, 0.f);
#pragma unroll
        for (int cc = 0; cc < CH; cc++) {
            const float4 p = *(const float4*)(g_KVpart + (size_t)(cc * BH + bh) * DD * DD + lin);
            s.x += p.x; s.y += p.y; s.z += p.z; s.w += p.w;
        }
        const int d = lin >> 6, m = lin & 63;
        *(float4*)(KVs + d * 68 + m) = s;
    }
#pragma unroll
    for (int i = 0; i < 4; i++) {
        const int lin = (tid + i * 256) * 4;
        const int j = lin >> 6, m = lin & 63;
        *(float4*)(Ws + j * 68 + m) = *(const float4*)(W_out + (size_t)j * HD + h * DD + m);
    }
    if (tid < 64) {
        float s = 0.0f;
#pragma unroll
        for (int cc = 0; cc < CH; cc++) s += g_KSpart[(cc * BH + bh) * DD + tid];
        g_Ksum[bh * DD + tid] = s;
    }
    __syncthreads();

    const int ty = tid >> 4;
    const int tx = tid & 15;
    float fa[4][4];
#pragma unroll
    for (int i = 0; i < 4; i++)
#pragma unroll
        for (int j = 0; j < 4; j++) fa[i][j] = 0.0f;
#pragma unroll 8
    for (int m = 0; m < 64; m++) {
        float a[4], w[4];
#pragma unroll
        for (int i = 0; i < 4; i++) a[i] = KVs[(ty * 4 + i) * 68 + m];
#pragma unroll
        for (int j = 0; j < 4; j++) w[j] = Ws[(tx * 4 + j) * 68 + m];
#pragma unroll
        for (int i = 0; i < 4; i++)
#pragma unroll
            for (int j = 0; j < 4; j++) fa[i][j] += a[i] * w[j];
    }
    float* cp = g_C + (size_t)bh * DD * DD;
#pragma unroll
    for (int i = 0; i < 4; i++) {
        float4 w = make_float4(tf32r(fa[i][0]), tf32r(fa[i][1]),
                               tf32r(fa[i][2]), tf32r(fa[i][3]));
        *(float4*)(cp + (ty * 4 + i) * DD + tx * 4) = w;
    }
    if (tid == 0) g_cnt[bh] = 0;     // reset for graph replay
}

// ---------------------------------------------------------------------------
// Phase 2: out[t][j] = b[j] + sum_h Z[t,h]*(Qphi[t,h,:] @ C[b,h][:,j]).
// (identical to R12 — two head groups, dot-MMA Z, measured ~42us)
// ---------------------------------------------------------------------------
__global__ __launch_bounds__(256, 2) void out_kernel(
    const float* __restrict__ query, const float* __restrict__ b_out,
    float* __restrict__ out)
{
    __shared__ float Qp[2][64][QSTR];
    __shared__ float Cs[2][64][CSTR];
    __shared__ float Ksm[2][64];

    const int blk = blockIdx.x;
    const int b   = blk >> 6;               // NN/64 = 64 tiles per batch
    const int t0g = blk * 64;
    const int tid = threadIdx.x;
    const int lane = tid & 31, warp = tid >> 5;
    const int hs   = warp >> 2;             // head slot 0/1
    const int wq   = warp & 3;
    const int mRow = (wq & 1) * 32;
    const int nCol = (wq >> 1) * 32;
    const int ar = lane >> 2;
    const int ac = lane & 3;
    const int barid = 1 + hs;

    const int l   = tid & 127;
    const int rb  = l >> 4;                 // 0..7 row base (stride 8)
    const int cd4 = (l & 15) * 4;

    const float* qbase = query + (size_t)(t0g + rb) * HD + cd4;
    const float* cbase = g_C + (size_t)(b * HH) * DD * DD + rb * DD + cd4;
    const float* kbase = g_Ksum + (b * HH) * DD;

    float acc[2][4][4];
#pragma unroll
    for (int mi = 0; mi < 2; mi++)
#pragma unroll
        for (int ni = 0; ni < 4; ni++)
#pragma unroll
            for (int j = 0; j < 4; j++) acc[mi][ni][j] = 0.0f;

    float4 qbuf[8];
#pragma unroll
    for (int i = 0; i < 8; i++)
        qbuf[i] = *(const float4*)(qbase + hs * DD + (size_t)i * 8 * HD);

    for (int p = 0; p < 8; p++) {
        const int hd = 2 * p + hs;

#pragma unroll
        for (int i = 0; i < 8; i++)
            cpa16(&Cs[hs][rb + i * 8][cd4],
                  cbase + (size_t)hd * DD * DD + i * 8 * DD);
        CP_COMMIT();

        if (l < 16)
            *(float4*)&Ksm[hs][l * 4] = r4(*(const float4*)(kbase + hd * DD + l * 4));

#pragma unroll
        for (int i = 0; i < 8; i++)
            *(float4*)&Qp[hs][rb + i * 8][cd4] = r4(phi4(qbuf[i]));

        if (p < 7) {
#pragma unroll
            for (int i = 0; i < 8; i++)
                qbuf[i] = *(const float4*)(qbase + (hd + 2) * DD + (size_t)i * 8 * HD);
        }

        CP_WAIT(0);
        BAR_GRP(barid);

        float tacc[2][4][4];
        float dacc[2][4];
#pragma unroll
        for (int mi = 0; mi < 2; mi++) {
#pragma unroll
            for (int ni = 0; ni < 4; ni++)
#pragma unroll
                for (int j = 0; j < 4; j++) tacc[mi][ni][j] = 0.0f;
#pragma unroll
            for (int j = 0; j < 4; j++) dacc[mi][j] = 0.0f;
        }

#pragma unroll
        for (int kk = 0; kk < 8; kk++) {
            const int k0 = kk * 8;
            unsigned a[2][4];
#pragma unroll
            for (int mi = 0; mi < 2; mi++) {
                const int r = mRow + mi * 16 + ar;
                a[mi][0] = fb(Qp[hs][r    ][k0 + ac    ]);
                a[mi][1] = fb(Qp[hs][r + 8][k0 + ac    ]);
                a[mi][2] = fb(Qp[hs][r    ][k0 + ac + 4]);
                a[mi][3] = fb(Qp[hs][r + 8][k0 + ac + 4]);
            }
            const unsigned kb0 = fb(Ksm[hs][k0 + ac    ]);
            const unsigned kb1 = fb(Ksm[hs][k0 + ac + 4]);
#pragma unroll
            for (int mi = 0; mi < 2; mi++)
                mma_tf32(dacc[mi], a[mi][0], a[mi][1], a[mi][2], a[mi][3], kb0, kb1);
#pragma unroll
            for (int ni = 0; ni < 4; ni++) {
                const int nc = nCol + ni * 8 + ar;
                const unsigned b0 = fb(Cs[hs][k0 + ac    ][nc]);
                const unsigned b1 = fb(Cs[hs][k0 + ac + 4][nc]);
#pragma unroll
                for (int mi = 0; mi < 2; mi++)
                    mma_tf32(tacc[mi][ni], a[mi][0], a[mi][1], a[mi][2], a[mi][3], b0, b1);
            }
        }

#pragma unroll
        for (int mi = 0; mi < 2; mi++) {
            const float z0 = 1.0f / (dacc[mi][0] + EPSZ);
            const float z1 = 1.0f / (dacc[mi][2] + EPSZ);
#pragma unroll
            for (int ni = 0; ni < 4; ni++) {
                acc[mi][ni][0] += z0 * tacc[mi][ni][0];
                acc[mi][ni][1] += z0 * tacc[mi][ni][1];
                acc[mi][ni][2] += z1 * tacc[mi][ni][2];
                acc[mi][ni][3] += z1 * tacc[mi][ni][3];
            }
        }
        BAR_GRP(barid);
    }

    __syncthreads();
    if (hs == 1) {
#pragma unroll
        for (int mi = 0; mi < 2; mi++)
#pragma unroll
            for (int ni = 0; ni < 4; ni++) {
                const int r = mRow + mi * 16 + ar;
                const int ccol = nCol + ni * 8 + 2 * ac;
                *(float2*)&Cs[0][r    ][ccol] = make_float2(acc[mi][ni][0], acc[mi][ni][1]);
                *(float2*)&Cs[0][r + 8][ccol] = make_float2(acc[mi][ni][2], acc[mi][ni][3]);
            }
    }
    __syncthreads();
    if (hs == 0) {
#pragma unroll
        for (int mi = 0; mi < 2; mi++)
#pragma unroll
            for (int ni = 0; ni < 4; ni++) {
                const int r = mRow + mi * 16 + ar;
                const int ccol = nCol + ni * 8 + 2 * ac;
                const float bj0 = b_out[ccol], bj1 = b_out[ccol + 1];
                const float2 o0 = *(const float2*)&Cs[0][r    ][ccol];
                const float2 o1 = *(const float2*)&Cs[0][r + 8][ccol];
                *(float2*)(out + (size_t)(t0g + r) * DD + ccol) =
                    make_float2(acc[mi][ni][0] + o0.x + bj0, acc[mi][ni][1] + o0.y + bj1);
                *(float2*)(out + (size_t)(t0g + r + 8) * DD + ccol) =
                    make_float2(acc[mi][ni][2] + o1.x + bj0, acc[mi][ni][3] + o1.y + bj1);
            }
    }
}

// ---------------------------------------------------------------------------
extern "C" void kernel_launch(void* const* d_in, const int* in_sizes, int n_in,
                              void* d_out, int out_size)
{
    const float* q  = (const float*)d_in[0];
    const float* k  = (const float*)d_in[1];
    const float* v  = (const float*)d_in[2];
    const float* W  = (const float*)d_in[3];
    const float* bo = (const float*)d_in[4];
    float* out = (float*)d_out;

    static int attr_set = 0;
    if (!attr_set) {
        cudaFuncSetAttribute(kv_partial_kernel,
                             cudaFuncAttributeMaxDynamicSharedMemorySize, KV_SMEM);
        attr_set = 1;
    }

    kv_partial_kernel<<<BH * CH, 256, KV_SMEM>>>(k, v, W);
    out_kernel<<<NTILE, 256>>>(q, bo, out);
}

// round 14
// speedup vs baseline: 1.0643x; 1.0643x over previous
#include <cuda_runtime.h>

#define BB 4
#define NN 4096
#define HH 16
#define DD 64
#define HD (HH*DD)          // 1024
#define BH (BB*HH)          // 64
#define CH 16
#define CHTOK (NN/CH)       // 256
#define EPSZ 1e-6f
#define OTILE 32
#define NTILE (BB*NN/OTILE) // 512 token tiles

#define KVSTR 72            // ==8 mod 32: conflict-free frags
#define QSTR  68            // ==4 mod 32
#define CSTR  72

__device__ float g_KVpart[CH*BH*DD*DD];   // 16 MB
__device__ float g_KSpart[CH*BH*DD];
__device__ float g_C[BH*DD*DD];           // tf32-rna-pre-rounded
__device__ float g_Ksum[BH*DD];

__device__ __forceinline__ float phi(float x) { return x > 0.0f ? x + 1.0f : __expf(x); }

__device__ __forceinline__ float tf32r(float x) {
    unsigned u;
    asm("cvt.rna.tf32.f32 %0, %1;" : "=r"(u) : "f"(x));
    return __uint_as_float(u);
}
__device__ __forceinline__ float4 phi4(float4 v) {
    float4 r; r.x = phi(v.x); r.y = phi(v.y); r.z = phi(v.z); r.w = phi(v.w);
    return r;
}
__device__ __forceinline__ float4 r4(float4 v) {
    float4 r; r.x = tf32r(v.x); r.y = tf32r(v.y); r.z = tf32r(v.z); r.w = tf32r(v.w);
    return r;
}

__device__ __forceinline__ void mma_tf32(float c[4],
    unsigned a0, unsigned a1, unsigned a2, unsigned a3,
    unsigned b0, unsigned b1)
{
    asm volatile(
        "mma.sync.aligned.m16n8k8.row.col.f32.tf32.tf32.f32 "
        "{%0,%1,%2,%3},{%4,%5,%6,%7},{%8,%9},{%0,%1,%2,%3};"
        : "+f"(c[0]), "+f"(c[1]), "+f"(c[2]), "+f"(c[3])
        : "r"(a0), "r"(a1), "r"(a2), "r"(a3), "r"(b0), "r"(b1));
}
__device__ __forceinline__ unsigned fb(float x) { return __float_as_uint(x); }

__device__ __forceinline__ void cpa16(void* smem, const void* g) {
    unsigned s = (unsigned)__cvta_generic_to_shared(smem);
    asm volatile("cp.async.ca.shared.global [%0], [%1], 16;" :: "r"(s), "l"(g));
}
#define CP_COMMIT() asm volatile("cp.async.commit_group;")
#define CP_WAIT(n)  asm volatile("cp.async.wait_group %0;" :: "n"(n))
#define BAR_GRP(id) asm volatile("bar.sync %0, 128;" :: "r"(id) : "memory")

// ---------------------------------------------------------------------------
// Phase 1: partial KV[d][m] = sum_t phi(K[t][d]) * V[t][m], tf32 MMA.
// (identical to R12 — measured 36.4us)
// ---------------------------------------------------------------------------
__global__ __launch_bounds__(256, 4) void kv_partial_kernel(
    const float* __restrict__ key, const float* __restrict__ value)
{
    __shared__ float Ks[2][32][KVSTR];
    __shared__ float Vs[2][32][KVSTR];
    __shared__ float kpart[16][64];

    const int bx  = blockIdx.x;
    const int c   = bx % CH;
    const int bh  = bx / CH;
    const int b   = bh / HH;
    const int h   = bh % HH;
    const int tid = threadIdx.x;
    const int lane = tid & 31, warp = tid >> 5;
    const int dRow = (warp & 3) * 16;
    const int mCol = (warp >> 2) * 32;
    const int ar = lane >> 2;
    const int ac = lane & 3;

    const int t0i = tid >> 4;        // 0..15
    const int t1i = t0i + 16;
    const int d4  = (tid & 15) * 4;

    const int n0 = c * CHTOK;
    const size_t gbase = (size_t)(b * NN + n0) * HD + h * DD + d4;
    const float* kp0 = key   + gbase + (size_t)t0i * HD;
    const float* kp1 = key   + gbase + (size_t)t1i * HD;
    const float* vp0 = value + gbase + (size_t)t0i * HD;
    const float* vp1 = value + gbase + (size_t)t1i * HD;

    float acc[4][4];
#pragma unroll
    for (int nt = 0; nt < 4; nt++)
#pragma unroll
        for (int j = 0; j < 4; j++) acc[nt][j] = 0.0f;

    float4 ks4 = make_float4(0.f, 0.f, 0.f, 0.f);

    cpa16(&Ks[0][t0i][d4], kp0);
    cpa16(&Ks[0][t1i][d4], kp1);
    cpa16(&Vs[0][t0i][d4], vp0);
    cpa16(&Vs[0][t1i][d4], vp1);
    CP_COMMIT();

    const int NT = CHTOK / 32;
    for (int tile = 0; tile < NT; tile++) {
        const int cur = tile & 1;
        if (tile + 1 < NT) {
            const size_t off = (size_t)(tile + 1) * 32 * HD;
            const int nxt = cur ^ 1;
            cpa16(&Ks[nxt][t0i][d4], kp0 + off);
            cpa16(&Ks[nxt][t1i][d4], kp1 + off);
            cpa16(&Vs[nxt][t0i][d4], vp0 + off);
            cpa16(&Vs[nxt][t1i][d4], vp1 + off);
            CP_COMMIT();
            CP_WAIT(1);
        } else {
            CP_WAIT(0);
        }

        {
            const float4 p0 = phi4(*(const float4*)&Ks[cur][t0i][d4]);
            const float4 p1 = phi4(*(const float4*)&Ks[cur][t1i][d4]);
            *(float4*)&Ks[cur][t0i][d4] = r4(p0);
            *(float4*)&Ks[cur][t1i][d4] = r4(p1);
            ks4.x += p0.x + p1.x; ks4.y += p0.y + p1.y;
            ks4.z += p0.z + p1.z; ks4.w += p0.w + p1.w;
            *(float4*)&Vs[cur][t0i][d4] = r4(*(const float4*)&Vs[cur][t0i][d4]);
            *(float4*)&Vs[cur][t1i][d4] = r4(*(const float4*)&Vs[cur][t1i][d4]);
        }
        __syncthreads();

#pragma unroll
        for (int kk = 0; kk < 4; kk++) {
            const int k0 = kk * 8;
            const unsigned a0 = fb(Ks[cur][k0 + ac    ][dRow + ar    ]);
            const unsigned a1 = fb(Ks[cur][k0 + ac    ][dRow + ar + 8]);
            const unsigned a2 = fb(Ks[cur][k0 + ac + 4][dRow + ar    ]);
            const unsigned a3 = fb(Ks[cur][k0 + ac + 4][dRow + ar + 8]);
#pragma unroll
            for (int nt = 0; nt < 4; nt++) {
                const int nc = mCol + nt * 8 + ar;
                const unsigned b0 = fb(Vs[cur][k0 + ac    ][nc]);
                const unsigned b1 = fb(Vs[cur][k0 + ac + 4][nc]);
                mma_tf32(acc[nt], a0, a1, a2, a3, b0, b1);
            }
        }
        __syncthreads();
    }

    *(float4*)&kpart[t0i][d4] = ks4;
    __syncthreads();
    if (tid < 64) {
        float s = 0.0f;
#pragma unroll
        for (int r = 0; r < 16; r++) s += kpart[r][tid];
        g_KSpart[(c * BH + bh) * DD + tid] = s;
    }

    float* outp = g_KVpart + (size_t)(c * BH + bh) * DD * DD;
#pragma unroll
    for (int nt = 0; nt < 4; nt++) {
        const int col = mCol + nt * 8 + 2 * ac;
        const int r0  = dRow + ar;
        *(float2*)(outp + r0 * DD + col)       = make_float2(acc[nt][0], acc[nt][1]);
        *(float2*)(outp + (r0 + 8) * DD + col) = make_float2(acc[nt][2], acc[nt][3]);
    }
}

// ---------------------------------------------------------------------------
// Phase 1.5: fold, split by d-quarter; stores C tf32-rna-rounded.
// (identical to R12)
// ---------------------------------------------------------------------------
__global__ __launch_bounds__(256) void fold_kernel(const float* __restrict__ W_out)
{
    __shared__ float KVq[16][64];
    __shared__ float Ws[64][68];

    const int bh  = blockIdx.x >> 2;
    const int dq  = blockIdx.x & 3;
    const int h   = bh % HH;
    const int d0  = dq * 16;
    const int tid = threadIdx.x;

    {
        const int lin = tid * 4;
        const int d = lin >> 6, m = lin & 63;
        float4 s = make_float4(0.f, 0.f, 0.f, 0.f);
#pragma unroll
        for (int cc = 0; cc < CH; cc++) {
            const float4 p = *(const float4*)(g_KVpart +
                (size_t)(cc * BH + bh) * DD * DD + (d0 + d) * DD + m);
            s.x += p.x; s.y += p.y; s.z += p.z; s.w += p.w;
        }
        *(float4*)&KVq[d][m] = s;
    }
#pragma unroll
    for (int i = 0; i < 4; i++) {
        const int lin = (tid + i * 256) * 4;
        const int j = lin >> 6, m = lin & 63;
        *(float4*)&Ws[j][m] = *(const float4*)(W_out + (size_t)j * HD + h * DD + m);
    }
    if (dq == 0 && tid < 64) {
        float s = 0.0f;
#pragma unroll
        for (int cc = 0; cc < CH; cc++) s += g_KSpart[(cc * BH + bh) * DD + tid];
        g_Ksum[bh * DD + tid] = s;
    }
    __syncthreads();

    const int d  = tid >> 4;
    const int j4 = (tid & 15) * 4;
    float a0 = 0.f, a1 = 0.f, a2 = 0.f, a3 = 0.f;
#pragma unroll 8
    for (int m = 0; m < 64; m++) {
        const float a = KVq[d][m];
        a0 += a * Ws[j4    ][m];
        a1 += a * Ws[j4 + 1][m];
        a2 += a * Ws[j4 + 2][m];
        a3 += a * Ws[j4 + 3][m];
    }
    float* cp = g_C + (size_t)bh * DD * DD + (d0 + d) * DD + j4;
    *(float4*)cp = make_float4(tf32r(a0), tf32r(a1), tf32r(a2), tf32r(a3));
}

// ---------------------------------------------------------------------------
// Phase 2: out[t][j] = b[j] + sum_h Z[t,h]*(Qphi[t,h,:] @ C[b,h][:,j]).
// 32-token tiles -> 512 blocks (3.46 avg blocks/SM; fixes the occ=20.7%
// starvation ncu showed). Two 4-warp head groups (named barriers), warp
// tile 16x32, dot-MMA Z on the tensor pipe. launch_bounds(256,2).
// ---------------------------------------------------------------------------
__global__ __launch_bounds__(256, 2) void out_kernel(
    const float* __restrict__ query, const float* __restrict__ b_out,
    float* __restrict__ out)
{
    __shared__ float Qp[2][OTILE][QSTR];
    __shared__ float Cs[2][64][CSTR];
    __shared__ float Ksm[2][64];

    const int blk = blockIdx.x;
    const int b   = blk >> 7;               // NN/OTILE = 128 tiles per batch
    const int t0g = blk * OTILE;
    const int tid = threadIdx.x;
    const int lane = tid & 31, warp = tid >> 5;
    const int hs   = warp >> 2;             // head slot 0/1
    const int wq   = warp & 3;
    const int mRow = (wq & 1) * 16;
    const int nCol = (wq >> 1) * 32;
    const int ar = lane >> 2;
    const int ac = lane & 3;
    const int barid = 1 + hs;

    const int l   = tid & 127;
    const int rb  = l >> 4;                 // 0..7 row base (stride 8)
    const int cd4 = (l & 15) * 4;

    const float* qbase = query + (size_t)(t0g + rb) * HD + cd4;
    const float* cbase = g_C + (size_t)(b * HH) * DD * DD + rb * DD + cd4;
    const float* kbase = g_Ksum + (b * HH) * DD;

    float acc[4][4];
#pragma unroll
    for (int ni = 0; ni < 4; ni++)
#pragma unroll
        for (int j = 0; j < 4; j++) acc[ni][j] = 0.0f;

    float4 qbuf[4];
#pragma unroll
    for (int i = 0; i < 4; i++)
        qbuf[i] = *(const float4*)(qbase + hs * DD + (size_t)i * 8 * HD);

    for (int p = 0; p < 8; p++) {
        const int hd = 2 * p + hs;

        // cp.async full C tile for this head (lands during phi phase)
#pragma unroll
        for (int i = 0; i < 8; i++)
            cpa16(&Cs[hs][rb + i * 8][cd4],
                  cbase + (size_t)hd * DD * DD + i * 8 * DD);
        CP_COMMIT();

        // Ksum for this head -> smem, rna-rounded
        if (l < 16)
            *(float4*)&Ksm[hs][l * 4] = r4(*(const float4*)(kbase + hd * DD + l * 4));

        // store phase: phi + rna + store (32 rows)
#pragma unroll
        for (int i = 0; i < 4; i++)
            *(float4*)&Qp[hs][rb + i * 8][cd4] = r4(phi4(qbuf[i]));

        // hoisted prefetch: qbuf dead now
        if (p < 7) {
#pragma unroll
            for (int i = 0; i < 4; i++)
                qbuf[i] = *(const float4*)(qbase + (hd + 2) * DD + (size_t)i * 8 * HD);
        }

        CP_WAIT(0);
        BAR_GRP(barid);

        float tacc[4][4];
        float dacc[4];
#pragma unroll
        for (int ni = 0; ni < 4; ni++)
#pragma unroll
            for (int j = 0; j < 4; j++) tacc[ni][j] = 0.0f;
#pragma unroll
        for (int j = 0; j < 4; j++) dacc[j] = 0.0f;

#pragma unroll
        for (int kk = 0; kk < 8; kk++) {
            const int k0 = kk * 8;
            const int r = mRow + ar;
            const unsigned a0 = fb(Qp[hs][r    ][k0 + ac    ]);
            const unsigned a1 = fb(Qp[hs][r + 8][k0 + ac    ]);
            const unsigned a2 = fb(Qp[hs][r    ][k0 + ac + 4]);
            const unsigned a3 = fb(Qp[hs][r + 8][k0 + ac + 4]);
            const unsigned kb0 = fb(Ksm[hs][k0 + ac    ]);
            const unsigned kb1 = fb(Ksm[hs][k0 + ac + 4]);
            mma_tf32(dacc, a0, a1, a2, a3, kb0, kb1);
#pragma unroll
            for (int ni = 0; ni < 4; ni++) {
                const int nc = nCol + ni * 8 + ar;
                const unsigned b0 = fb(Cs[hs][k0 + ac    ][nc]);
                const unsigned b1 = fb(Cs[hs][k0 + ac + 4][nc]);
                mma_tf32(tacc[ni], a0, a1, a2, a3, b0, b1);
            }
        }

        const float z0 = 1.0f / (dacc[0] + EPSZ);
        const float z1 = 1.0f / (dacc[2] + EPSZ);
#pragma unroll
        for (int ni = 0; ni < 4; ni++) {
            acc[ni][0] += z0 * tacc[ni][0];
            acc[ni][1] += z0 * tacc[ni][1];
            acc[ni][2] += z1 * tacc[ni][2];
            acc[ni][3] += z1 * tacc[ni][3];
        }
        BAR_GRP(barid);
    }

    // merge head-group partials: slot1 -> smem, slot0 adds + bias + store
    __syncthreads();
    if (hs == 1) {
#pragma unroll
        for (int ni = 0; ni < 4; ni++) {
            const int r = mRow + ar;
            const int ccol = nCol + ni * 8 + 2 * ac;
            *(float2*)&Cs[0][r    ][ccol] = make_float2(acc[ni][0], acc[ni][1]);
            *(float2*)&Cs[0][r + 8][ccol] = make_float2(acc[ni][2], acc[ni][3]);
        }
    }
    __syncthreads();
    if (hs == 0) {
#pragma unroll
        for (int ni = 0; ni < 4; ni++) {
            const int r = mRow + ar;
            const int ccol = nCol + ni * 8 + 2 * ac;
            const float bj0 = b_out[ccol], bj1 = b_out[ccol + 1];
            const float2 o0 = *(const float2*)&Cs[0][r    ][ccol];
            const float2 o1 = *(const float2*)&Cs[0][r + 8][ccol];
            *(float2*)(out + (size_t)(t0g + r) * DD + ccol) =
                make_float2(acc[ni][0] + o0.x + bj0, acc[ni][1] + o0.y + bj1);
            *(float2*)(out + (size_t)(t0g + r + 8) * DD + ccol) =
                make_float2(acc[ni][2] + o1.x + bj0, acc[ni][3] + o1.y + bj1);
        }
    }
}

// ---------------------------------------------------------------------------
extern "C" void kernel_launch(void* const* d_in, const int* in_sizes, int n_in,
                              void* d_out, int out_size)
{
    const float* q  = (const float*)d_in[0];
    const float* k  = (const float*)d_in[1];
    const float* v  = (const float*)d_in[2];
    const float* W  = (const float*)d_in[3];
    const float* bo = (const float*)d_in[4];
    float* out = (float*)d_out;

    kv_partial_kernel<<<BH * CH, 256>>>(k, v);
    fold_kernel<<<BH * 4, 256>>>(W);
    out_kernel<<<NTILE, 256>>>(q, bo, out);
}

// round 15
// speedup vs baseline: 1.1401x; 1.0712x over previous
#include <cuda_runtime.h>

#define BB 4
#define NN 4096
#define HH 16
#define DD 64
#define HD (HH*DD)          // 1024
#define BH (BB*HH)          // 64
#define CH 16
#define CHTOK (NN/CH)       // 256
#define EPSZ 1e-6f
#define NTILE (BB*NN/64)    // 256 token tiles

#define KVSTR 72            // ==8 mod 32: conflict-free frags
#define QSTR  68            // ==4 mod 32
#define CSTR  72

__device__ float g_KVpart[CH*BH*DD*DD];   // 16 MB
__device__ float g_KSpart[CH*BH*DD];
__device__ float g_C[BH*DD*DD];           // tf32-rna-pre-rounded
__device__ float g_Ksum[BH*DD];

__device__ __forceinline__ float phi(float x) { return x > 0.0f ? x + 1.0f : __expf(x); }

__device__ __forceinline__ float tf32r(float x) {
    unsigned u;
    asm("cvt.rna.tf32.f32 %0, %1;" : "=r"(u) : "f"(x));
    return __uint_as_float(u);
}
__device__ __forceinline__ float4 phi4(float4 v) {
    float4 r; r.x = phi(v.x); r.y = phi(v.y); r.z = phi(v.z); r.w = phi(v.w);
    return r;
}
__device__ __forceinline__ float4 r4(float4 v) {
    float4 r; r.x = tf32r(v.x); r.y = tf32r(v.y); r.z = tf32r(v.z); r.w = tf32r(v.w);
    return r;
}

__device__ __forceinline__ void mma_tf32(float c[4],
    unsigned a0, unsigned a1, unsigned a2, unsigned a3,
    unsigned b0, unsigned b1)
{
    asm volatile(
        "mma.sync.aligned.m16n8k8.row.col.f32.tf32.tf32.f32 "
        "{%0,%1,%2,%3},{%4,%5,%6,%7},{%8,%9},{%0,%1,%2,%3};"
        : "+f"(c[0]), "+f"(c[1]), "+f"(c[2]), "+f"(c[3])
        : "r"(a0), "r"(a1), "r"(a2), "r"(a3), "r"(b0), "r"(b1));
}
__device__ __forceinline__ unsigned fb(float x) { return __float_as_uint(x); }

__device__ __forceinline__ void cpa16(void* smem, const void* g) {
    unsigned s = (unsigned)__cvta_generic_to_shared(smem);
    asm volatile("cp.async.ca.shared.global [%0], [%1], 16;" :: "r"(s), "l"(g));
}
#define CP_COMMIT() asm volatile("cp.async.commit_group;")
#define CP_WAIT(n)  asm volatile("cp.async.wait_group %0;" :: "n"(n))
#define BAR_GRP(id) asm volatile("bar.sync %0, 128;" :: "r"(id) : "memory")

// ---------------------------------------------------------------------------
// Phase 1: partial KV[d][m] = sum_t phi(K[t][d]) * V[t][m], tf32 MMA.
// 128 threads / 4 warps, each warp owns a 32x32 quadrant (2.0 LDS per MMA
// vs 3.0 at 16x32). 2-stage cp.async pipeline (commit-at-top, wait(1)),
// RMW phi+rna / rna, register Ksum. 1024 blocks x 128 threads.
// ---------------------------------------------------------------------------
__global__ __launch_bounds__(128, 5) void kv_partial_kernel(
    const float* __restrict__ key, const float* __restrict__ value)
{
    __shared__ float Ks[2][32][KVSTR];
    __shared__ float Vs[2][32][KVSTR];
    __shared__ float kpart[8][64];

    const int bx  = blockIdx.x;
    const int c   = bx % CH;
    const int bh  = bx / CH;
    const int b   = bh / HH;
    const int h   = bh % HH;
    const int tid = threadIdx.x;
    const int lane = tid & 31, warp = tid >> 5;  // 0..3
    const int dRow = (warp & 1) * 32;
    const int mCol = (warp >> 1) * 32;
    const int ar = lane >> 2;
    const int ac = lane & 3;

    const int ti  = tid >> 4;        // 0..7 (rows ti, ti+8, ti+16, ti+24)
    const int d4  = (tid & 15) * 4;

    const int n0 = c * CHTOK;
    const size_t gbase = (size_t)(b * NN + n0) * HD + h * DD + d4;
    const float* kp = key   + gbase + (size_t)ti * HD;
    const float* vp = value + gbase + (size_t)ti * HD;

    float acc[2][4][4];
#pragma unroll
    for (int mi = 0; mi < 2; mi++)
#pragma unroll
        for (int ni = 0; ni < 4; ni++)
#pragma unroll
            for (int j = 0; j < 4; j++) acc[mi][ni][j] = 0.0f;

    float4 ks4 = make_float4(0.f, 0.f, 0.f, 0.f);

    // prologue: tile 0 -> stage 0 (4 K-chunks + 4 V-chunks per thread)
#pragma unroll
    for (int i = 0; i < 4; i++) {
        cpa16(&Ks[0][ti + i * 8][d4], kp + (size_t)i * 8 * HD);
        cpa16(&Vs[0][ti + i * 8][d4], vp + (size_t)i * 8 * HD);
    }
    CP_COMMIT();

    const int NT = CHTOK / 32;       // 8
    for (int tile = 0; tile < NT; tile++) {
        const int cur = tile & 1;
        if (tile + 1 < NT) {
            const size_t off = (size_t)(tile + 1) * 32 * HD;
            const int nxt = cur ^ 1;
#pragma unroll
            for (int i = 0; i < 4; i++) {
                cpa16(&Ks[nxt][ti + i * 8][d4], kp + off + (size_t)i * 8 * HD);
                cpa16(&Vs[nxt][ti + i * 8][d4], vp + off + (size_t)i * 8 * HD);
            }
            CP_COMMIT();
            CP_WAIT(1);
        } else {
            CP_WAIT(0);
        }

        // RMW convert own chunks; accumulate Ksum from registers
#pragma unroll
        for (int i = 0; i < 4; i++) {
            const int t = ti + i * 8;
            const float4 p = phi4(*(const float4*)&Ks[cur][t][d4]);
            *(float4*)&Ks[cur][t][d4] = r4(p);
            ks4.x += p.x; ks4.y += p.y; ks4.z += p.z; ks4.w += p.w;
            *(float4*)&Vs[cur][t][d4] = r4(*(const float4*)&Vs[cur][t][d4]);
        }
        __syncthreads();

#pragma unroll
        for (int kk = 0; kk < 4; kk++) {
            const int k0 = kk * 8;
            unsigned a[2][4];
#pragma unroll
            for (int mi = 0; mi < 2; mi++) {
                const int base = dRow + 16 * mi;
                a[mi][0] = fb(Ks[cur][k0 + ac    ][base + ar    ]);
                a[mi][1] = fb(Ks[cur][k0 + ac    ][base + ar + 8]);
                a[mi][2] = fb(Ks[cur][k0 + ac + 4][base + ar    ]);
                a[mi][3] = fb(Ks[cur][k0 + ac + 4][base + ar + 8]);
            }
#pragma unroll
            for (int ni = 0; ni < 4; ni++) {
                const int nc = mCol + ni * 8 + ar;
                const unsigned b0 = fb(Vs[cur][k0 + ac    ][nc]);
                const unsigned b1 = fb(Vs[cur][k0 + ac + 4][nc]);
#pragma unroll
                for (int mi = 0; mi < 2; mi++)
                    mma_tf32(acc[mi][ni], a[mi][0], a[mi][1], a[mi][2], a[mi][3], b0, b1);
            }
        }
        __syncthreads();
    }

    // Ksum reduce: each thread owns unique (ti, d4) slot
    *(float4*)&kpart[ti][d4] = ks4;
    __syncthreads();
    if (tid < 64) {
        float s = 0.0f;
#pragma unroll
        for (int r = 0; r < 8; r++) s += kpart[r][tid];
        g_KSpart[(c * BH + bh) * DD + tid] = s;
    }

    float* outp = g_KVpart + (size_t)(c * BH + bh) * DD * DD;
#pragma unroll
    for (int mi = 0; mi < 2; mi++)
#pragma unroll
        for (int ni = 0; ni < 4; ni++) {
            const int col = mCol + ni * 8 + 2 * ac;
            const int r0  = dRow + 16 * mi + ar;
            *(float2*)(outp + r0 * DD + col)       = make_float2(acc[mi][ni][0], acc[mi][ni][1]);
            *(float2*)(outp + (r0 + 8) * DD + col) = make_float2(acc[mi][ni][2], acc[mi][ni][3]);
        }
}

// ---------------------------------------------------------------------------
// Phase 1.5: fold, split by d-quarter; stores C tf32-rna-rounded.
// (identical to R12)
// ---------------------------------------------------------------------------
__global__ __launch_bounds__(256) void fold_kernel(const float* __restrict__ W_out)
{
    __shared__ float KVq[16][64];
    __shared__ float Ws[64][68];

    const int bh  = blockIdx.x >> 2;
    const int dq  = blockIdx.x & 3;
    const int h   = bh % HH;
    const int d0  = dq * 16;
    const int tid = threadIdx.x;

    {
        const int lin = tid * 4;
        const int d = lin >> 6, m = lin & 63;
        float4 s = make_float4(0.f, 0.f, 0.f, 0.f);
#pragma unroll
        for (int cc = 0; cc < CH; cc++) {
            const float4 p = *(const float4*)(g_KVpart +
                (size_t)(cc * BH + bh) * DD * DD + (d0 + d) * DD + m);
            s.x += p.x; s.y += p.y; s.z += p.z; s.w += p.w;
        }
        *(float4*)&KVq[d][m] = s;
    }
#pragma unroll
    for (int i = 0; i < 4; i++) {
        const int lin = (tid + i * 256) * 4;
        const int j = lin >> 6, m = lin & 63;
        *(float4*)&Ws[j][m] = *(const float4*)(W_out + (size_t)j * HD + h * DD + m);
    }
    if (dq == 0 && tid < 64) {
        float s = 0.0f;
#pragma unroll
        for (int cc = 0; cc < CH; cc++) s += g_KSpart[(cc * BH + bh) * DD + tid];
        g_Ksum[bh * DD + tid] = s;
    }
    __syncthreads();

    const int d  = tid >> 4;
    const int j4 = (tid & 15) * 4;
    float a0 = 0.f, a1 = 0.f, a2 = 0.f, a3 = 0.f;
#pragma unroll 8
    for (int m = 0; m < 64; m++) {
        const float a = KVq[d][m];
        a0 += a * Ws[j4    ][m];
        a1 += a * Ws[j4 + 1][m];
        a2 += a * Ws[j4 + 2][m];
        a3 += a * Ws[j4 + 3][m];
    }
    float* cp = g_C + (size_t)bh * DD * DD + (d0 + d) * DD + j4;
    *(float4*)cp = make_float4(tf32r(a0), tf32r(a1), tf32r(a2), tf32r(a3));
}

// ---------------------------------------------------------------------------
// Phase 2: out[t][j] = b[j] + sum_h Z[t,h]*(Qphi[t,h,:] @ C[b,h][:,j]).
// (identical to R12 — 64-token tiles, two head groups, dot-MMA Z)
// ---------------------------------------------------------------------------
__global__ __launch_bounds__(256, 2) void out_kernel(
    const float* __restrict__ query, const float* __restrict__ b_out,
    float* __restrict__ out)
{
    __shared__ float Qp[2][64][QSTR];
    __shared__ float Cs[2][64][CSTR];
    __shared__ float Ksm[2][64];

    const int blk = blockIdx.x;
    const int b   = blk >> 6;               // NN/64 = 64 tiles per batch
    const int t0g = blk * 64;
    const int tid = threadIdx.x;
    const int lane = tid & 31, warp = tid >> 5;
    const int hs   = warp >> 2;             // head slot 0/1
    const int wq   = warp & 3;
    const int mRow = (wq & 1) * 32;
    const int nCol = (wq >> 1) * 32;
    const int ar = lane >> 2;
    const int ac = lane & 3;
    const int barid = 1 + hs;

    const int l   = tid & 127;
    const int rb  = l >> 4;                 // 0..7 row base (stride 8)
    const int cd4 = (l & 15) * 4;

    const float* qbase = query + (size_t)(t0g + rb) * HD + cd4;
    const float* cbase = g_C + (size_t)(b * HH) * DD * DD + rb * DD + cd4;
    const float* kbase = g_Ksum + (b * HH) * DD;

    float acc[2][4][4];
#pragma unroll
    for (int mi = 0; mi < 2; mi++)
#pragma unroll
        for (int ni = 0; ni < 4; ni++)
#pragma unroll
            for (int j = 0; j < 4; j++) acc[mi][ni][j] = 0.0f;

    float4 qbuf[8];
#pragma unroll
    for (int i = 0; i < 8; i++)
        qbuf[i] = *(const float4*)(qbase + hs * DD + (size_t)i * 8 * HD);

    for (int p = 0; p < 8; p++) {
        const int hd = 2 * p + hs;

#pragma unroll
        for (int i = 0; i < 8; i++)
            cpa16(&Cs[hs][rb + i * 8][cd4],
                  cbase + (size_t)hd * DD * DD + i * 8 * DD);
        CP_COMMIT();

        if (l < 16)
            *(float4*)&Ksm[hs][l * 4] = r4(*(const float4*)(kbase + hd * DD + l * 4));

#pragma unroll
        for (int i = 0; i < 8; i++)
            *(float4*)&Qp[hs][rb + i * 8][cd4] = r4(phi4(qbuf[i]));

        if (p < 7) {
#pragma unroll
            for (int i = 0; i < 8; i++)
                qbuf[i] = *(const float4*)(qbase + (hd + 2) * DD + (size_t)i * 8 * HD);
        }

        CP_WAIT(0);
        BAR_GRP(barid);

        float tacc[2][4][4];
        float dacc[2][4];
#pragma unroll
        for (int mi = 0; mi < 2; mi++) {
#pragma unroll
            for (int ni = 0; ni < 4; ni++)
#pragma unroll
                for (int j = 0; j < 4; j++) tacc[mi][ni][j] = 0.0f;
#pragma unroll
            for (int j = 0; j < 4; j++) dacc[mi][j] = 0.0f;
        }

#pragma unroll
        for (int kk = 0; kk < 8; kk++) {
            const int k0 = kk * 8;
            unsigned a[2][4];
#pragma unroll
            for (int mi = 0; mi < 2; mi++) {
                const int r = mRow + mi * 16 + ar;
                a[mi][0] = fb(Qp[hs][r    ][k0 + ac    ]);
                a[mi][1] = fb(Qp[hs][r + 8][k0 + ac    ]);
                a[mi][2] = fb(Qp[hs][r    ][k0 + ac + 4]);
                a[mi][3] = fb(Qp[hs][r + 8][k0 + ac + 4]);
            }
            const unsigned kb0 = fb(Ksm[hs][k0 + ac    ]);
            const unsigned kb1 = fb(Ksm[hs][k0 + ac + 4]);
#pragma unroll
            for (int mi = 0; mi < 2; mi++)
                mma_tf32(dacc[mi], a[mi][0], a[mi][1], a[mi][2], a[mi][3], kb0, kb1);
#pragma unroll
            for (int ni = 0; ni < 4; ni++) {
                const int nc = nCol + ni * 8 + ar;
                const unsigned b0 = fb(Cs[hs][k0 + ac    ][nc]);
                const unsigned b1 = fb(Cs[hs][k0 + ac + 4][nc]);
#pragma unroll
                for (int mi = 0; mi < 2; mi++)
                    mma_tf32(tacc[mi][ni], a[mi][0], a[mi][1], a[mi][2], a[mi][3], b0, b1);
            }
        }

#pragma unroll
        for (int mi = 0; mi < 2; mi++) {
            const float z0 = 1.0f / (dacc[mi][0] + EPSZ);
            const float z1 = 1.0f / (dacc[mi][2] + EPSZ);
#pragma unroll
            for (int ni = 0; ni < 4; ni++) {
                acc[mi][ni][0] += z0 * tacc[mi][ni][0];
                acc[mi][ni][1] += z0 * tacc[mi][ni][1];
                acc[mi][ni][2] += z1 * tacc[mi][ni][2];
                acc[mi][ni][3] += z1 * tacc[mi][ni][3];
            }
        }
        BAR_GRP(barid);
    }

    __syncthreads();
    if (hs == 1) {
#pragma unroll
        for (int mi = 0; mi < 2; mi++)
#pragma unroll
            for (int ni = 0; ni < 4; ni++) {
                const int r = mRow + mi * 16 + ar;
                const int ccol = nCol + ni * 8 + 2 * ac;
                *(float2*)&Cs[0][r    ][ccol] = make_float2(acc[mi][ni][0], acc[mi][ni][1]);
                *(float2*)&Cs[0][r + 8][ccol] = make_float2(acc[mi][ni][2], acc[mi][ni][3]);
            }
    }
    __syncthreads();
    if (hs == 0) {
#pragma unroll
        for (int mi = 0; mi < 2; mi++)
#pragma unroll
            for (int ni = 0; ni < 4; ni++) {
                const int r = mRow + mi * 16 + ar;
                const int ccol = nCol + ni * 8 + 2 * ac;
                const float bj0 = b_out[ccol], bj1 = b_out[ccol + 1];
                const float2 o0 = *(const float2*)&Cs[0][r    ][ccol];
                const float2 o1 = *(const float2*)&Cs[0][r + 8][ccol];
                *(float2*)(out + (size_t)(t0g + r) * DD + ccol) =
                    make_float2(acc[mi][ni][0] + o0.x + bj0, acc[mi][ni][1] + o0.y + bj1);
                *(float2*)(out + (size_t)(t0g + r + 8) * DD + ccol) =
                    make_float2(acc[mi][ni][2] + o1.x + bj0, acc[mi][ni][3] + o1.y + bj1);
            }
    }
}

// ---------------------------------------------------------------------------
extern "C" void kernel_launch(void* const* d_in, const int* in_sizes, int n_in,
                              void* d_out, int out_size)
{
    const float* q  = (const float*)d_in[0];
    const float* k  = (const float*)d_in[1];
    const float* v  = (const float*)d_in[2];
    const float* W  = (const float*)d_in[3];
    const float* bo = (const float*)d_in[4];
    float* out = (float*)d_out;

    kv_partial_kernel<<<BH * CH, 128>>>(k, v);
    fold_kernel<<<BH * 4, 256>>>(W);
    out_kernel<<<NTILE, 256>>>(q, bo, out);
}